// round 1
// baseline (speedup 1.0000x reference)
#include <cuda_runtime.h>
#include <cuda_bf16.h>

// RiskAwareMAE: losses = max((f-1)*e, f*e), e = t - o,
// f = (nearest_percentile_idx(t) + 1) / P, percentiles are a uniform linspace.
// mean over N=2^24.  Pure HBM-bound streaming reduction (134 MB reads).

#define NBLOCKS 1216          // ~one wave on 152 SMs at 8 CTAs/SM
#define NTHREADS 256
#define NWARPS (NTHREADS / 32)

__device__ float g_partials[NBLOCKS];

__device__ __forceinline__ float warp_reduce(float v) {
#pragma unroll
    for (int off = 16; off > 0; off >>= 1)
        v += __shfl_xor_sync(0xFFFFFFFFu, v, off);
    return v;
}

__device__ __forceinline__ float loss_elem(float o, float t,
                                           float p0, float inv_step,
                                           float invP, float Pm1) {
    // nearest bin on uniform grid: round((t - p0) / step), clamped
    float j = rintf((t - p0) * inv_step);
    j = fminf(fmaxf(j, 0.0f), Pm1);
    float factor = (j + 1.0f) * invP;
    float e = t - o;
    return fmaxf((factor - 1.0f) * e, factor * e);
}

__global__ void __launch_bounds__(NTHREADS)
risk_mae_partial(const float4* __restrict__ out4,
                 const float4* __restrict__ tgt4,
                 const float* __restrict__ perc,
                 int n4, int P) {
    const float p0 = __ldg(&perc[0]);
    const float pl = __ldg(&perc[P - 1]);
    const float Pm1 = (float)(P - 1);
    const float inv_step = Pm1 / (pl - p0);
    const float invP = 1.0f / (float)P;

    float acc = 0.0f;
    const int stride = gridDim.x * blockDim.x;
    int i = blockIdx.x * blockDim.x + threadIdx.x;
#pragma unroll 4
    for (; i < n4; i += stride) {
        float4 o = out4[i];
        float4 t = tgt4[i];
        acc += loss_elem(o.x, t.x, p0, inv_step, invP, Pm1);
        acc += loss_elem(o.y, t.y, p0, inv_step, invP, Pm1);
        acc += loss_elem(o.z, t.z, p0, inv_step, invP, Pm1);
        acc += loss_elem(o.w, t.w, p0, inv_step, invP, Pm1);
    }

    // block reduction: warp shuffle, then cross-warp via shared
    __shared__ float smem[NWARPS];
    acc = warp_reduce(acc);
    int wid = threadIdx.x >> 5;
    int lid = threadIdx.x & 31;
    if (lid == 0) smem[wid] = acc;
    __syncthreads();
    if (wid == 0) {
        float v = (lid < NWARPS) ? smem[lid] : 0.0f;
        v = warp_reduce(v);
        if (lid == 0) g_partials[blockIdx.x] = v;
    }
}

__global__ void __launch_bounds__(1024)
risk_mae_final(float* __restrict__ d_out, int nblocks, float inv_n) {
    __shared__ double smem[32];
    double acc = 0.0;
    for (int i = threadIdx.x; i < nblocks; i += 1024)
        acc += (double)g_partials[i];
#pragma unroll
    for (int off = 16; off > 0; off >>= 1)
        acc += __shfl_xor_sync(0xFFFFFFFFu, acc, off);
    int wid = threadIdx.x >> 5;
    int lid = threadIdx.x & 31;
    if (lid == 0) smem[wid] = acc;
    __syncthreads();
    if (wid == 0) {
        double v = (lid < 32) ? smem[lid] : 0.0;
#pragma unroll
        for (int off = 16; off > 0; off >>= 1)
            v += __shfl_xor_sync(0xFFFFFFFFu, v, off);
        if (lid == 0) d_out[0] = (float)(v * (double)inv_n);
    }
}

extern "C" void kernel_launch(void* const* d_in, const int* in_sizes, int n_in,
                              void* d_out, int out_size) {
    const float* outputs = (const float*)d_in[0];
    const float* targets = (const float*)d_in[1];
    const float* percentiles = (const float*)d_in[2];
    const int n = in_sizes[0];
    const int P = in_sizes[2];
    const int n4 = n / 4;

    risk_mae_partial<<<NBLOCKS, NTHREADS>>>(
        (const float4*)outputs, (const float4*)targets, percentiles, n4, P);
    risk_mae_final<<<1, 1024>>>((float*)d_out, NBLOCKS, 1.0f / (float)n);
}

// round 2
// speedup vs baseline: 1.0111x; 1.0111x over previous
#include <cuda_runtime.h>
#include <cuda_bf16.h>

// RiskAwareMAE: losses = max((f-1)*e, f*e), e = t - o,
// f = (nearest_percentile_idx(t) + 1) / P, percentiles uniform linspace.
// Single-kernel streaming reduction with threadfence last-block finish.

#define NBLOCKS 1216          // 8 CTAs/SM on 152 SMs
#define NTHREADS 256
#define NWARPS (NTHREADS / 32)

__device__ float g_partials[NBLOCKS];
__device__ unsigned int g_ticket = 0;   // wraps back to 0 via atomicInc modulo

__device__ __forceinline__ float warp_reduce(float v) {
#pragma unroll
    for (int off = 16; off > 0; off >>= 1)
        v += __shfl_xor_sync(0xFFFFFFFFu, v, off);
    return v;
}

__device__ __forceinline__ float loss_elem(float o, float t,
                                           float p0, float inv_step,
                                           float invP, float Pm1) {
    float j = rintf((t - p0) * inv_step);
    j = fminf(fmaxf(j, 0.0f), Pm1);
    float factor = (j + 1.0f) * invP;
    float e = t - o;
    return fmaxf((factor - 1.0f) * e, factor * e);
}

__global__ void __launch_bounds__(NTHREADS)
risk_mae_fused(const float4* __restrict__ out4,
               const float4* __restrict__ tgt4,
               const float* __restrict__ perc,
               float* __restrict__ d_out,
               int n4, int P, float inv_n) {
    const float p0 = __ldg(&perc[0]);
    const float pl = __ldg(&perc[P - 1]);
    const float Pm1 = (float)(P - 1);
    const float inv_step = Pm1 / (pl - p0);
    const float invP = 1.0f / (float)P;

    const int stride = gridDim.x * blockDim.x;
    int i = blockIdx.x * blockDim.x + threadIdx.x;

    float acc = 0.0f;

    // 4-way batched main loop: 8 independent float4 loads issued up front (MLP~8)
    for (; i + 3 * stride < n4; i += 4 * stride) {
        float4 o0 = out4[i];
        float4 o1 = out4[i + stride];
        float4 o2 = out4[i + 2 * stride];
        float4 o3 = out4[i + 3 * stride];
        float4 t0 = tgt4[i];
        float4 t1 = tgt4[i + stride];
        float4 t2 = tgt4[i + 2 * stride];
        float4 t3 = tgt4[i + 3 * stride];
        acc += loss_elem(o0.x, t0.x, p0, inv_step, invP, Pm1);
        acc += loss_elem(o0.y, t0.y, p0, inv_step, invP, Pm1);
        acc += loss_elem(o0.z, t0.z, p0, inv_step, invP, Pm1);
        acc += loss_elem(o0.w, t0.w, p0, inv_step, invP, Pm1);
        acc += loss_elem(o1.x, t1.x, p0, inv_step, invP, Pm1);
        acc += loss_elem(o1.y, t1.y, p0, inv_step, invP, Pm1);
        acc += loss_elem(o1.z, t1.z, p0, inv_step, invP, Pm1);
        acc += loss_elem(o1.w, t1.w, p0, inv_step, invP, Pm1);
        acc += loss_elem(o2.x, t2.x, p0, inv_step, invP, Pm1);
        acc += loss_elem(o2.y, t2.y, p0, inv_step, invP, Pm1);
        acc += loss_elem(o2.z, t2.z, p0, inv_step, invP, Pm1);
        acc += loss_elem(o2.w, t2.w, p0, inv_step, invP, Pm1);
        acc += loss_elem(o3.x, t3.x, p0, inv_step, invP, Pm1);
        acc += loss_elem(o3.y, t3.y, p0, inv_step, invP, Pm1);
        acc += loss_elem(o3.z, t3.z, p0, inv_step, invP, Pm1);
        acc += loss_elem(o3.w, t3.w, p0, inv_step, invP, Pm1);
    }
    for (; i < n4; i += stride) {
        float4 o = out4[i];
        float4 t = tgt4[i];
        acc += loss_elem(o.x, t.x, p0, inv_step, invP, Pm1);
        acc += loss_elem(o.y, t.y, p0, inv_step, invP, Pm1);
        acc += loss_elem(o.z, t.z, p0, inv_step, invP, Pm1);
        acc += loss_elem(o.w, t.w, p0, inv_step, invP, Pm1);
    }

    // block reduction
    __shared__ float smem[NWARPS];
    acc = warp_reduce(acc);
    int wid = threadIdx.x >> 5;
    int lid = threadIdx.x & 31;
    if (lid == 0) smem[wid] = acc;
    __syncthreads();
    if (wid == 0) {
        float v = (lid < NWARPS) ? smem[lid] : 0.0f;
        v = warp_reduce(v);
        if (lid == 0) g_partials[blockIdx.x] = v;
    }

    // last-block final reduction (threadfence reduction pattern).
    // atomicInc wraps to 0 after NBLOCKS arrivals -> clean state for graph replay.
    __shared__ bool s_last;
    __threadfence();
    if (threadIdx.x == 0) {
        unsigned int ticket = atomicInc(&g_ticket, NBLOCKS - 1);
        s_last = (ticket == NBLOCKS - 1);
    }
    __syncthreads();
    if (s_last) {
        // deterministic: each thread sums a fixed strided subset in fixed order
        double dacc = 0.0;
        for (int k = threadIdx.x; k < NBLOCKS; k += NTHREADS)
            dacc = dacc + (double)g_partials[k];
#pragma unroll
        for (int off = 16; off > 0; off >>= 1)
            dacc += __shfl_xor_sync(0xFFFFFFFFu, dacc, off);
        __shared__ double dsm[NWARPS];
        if (lid == 0) dsm[wid] = dacc;
        __syncthreads();
        if (wid == 0) {
            double v = (lid < NWARPS) ? dsm[lid] : 0.0;
#pragma unroll
            for (int off = 16; off > 0; off >>= 1)
                v += __shfl_xor_sync(0xFFFFFFFFu, v, off);
            if (lid == 0) d_out[0] = (float)(v * (double)inv_n);
        }
    }
}

extern "C" void kernel_launch(void* const* d_in, const int* in_sizes, int n_in,
                              void* d_out, int out_size) {
    const float* outputs = (const float*)d_in[0];
    const float* targets = (const float*)d_in[1];
    const float* percentiles = (const float*)d_in[2];
    const int n = in_sizes[0];
    const int P = in_sizes[2];
    const int n4 = n / 4;

    risk_mae_fused<<<NBLOCKS, NTHREADS>>>(
        (const float4*)outputs, (const float4*)targets, percentiles,
        (float*)d_out, n4, P, 1.0f / (float)n);
}